// round 1
// baseline (speedup 1.0000x reference)
#include <cuda_runtime.h>
#include <math.h>

#define TOK   4096      // B*N tokens
#define DIM   1024
#define MLPD  4096
#define NHEAD 16
#define HD    64
#define SEQ   2048

// ---------------- scratch (no allocations allowed) ----------------
__device__ float g_xln [TOK * DIM];
__device__ float g_qkv [TOK * 3 * DIM];
__device__ float g_attn[TOK * DIM];
__device__ float g_x1  [TOK * DIM];
__device__ float g_xln2[TOK * DIM];
__device__ float g_h   [TOK * MLPD];

// ---------------- LayerNorm: one block per row ----------------
__global__ __launch_bounds__(256) void ln_kernel(
    const float* __restrict__ x, const float* __restrict__ w,
    const float* __restrict__ b, float* __restrict__ out)
{
    int row = blockIdx.x;
    int tid = threadIdx.x;
    const float4* xr = (const float4*)(x + (size_t)row * DIM);
    float4 v = xr[tid];

    __shared__ float red[9];
    float s = v.x + v.y + v.z + v.w;
    #pragma unroll
    for (int o = 16; o > 0; o >>= 1) s += __shfl_xor_sync(0xffffffffu, s, o);
    if ((tid & 31) == 0) red[tid >> 5] = s;
    __syncthreads();
    if (tid == 0) {
        float t = 0.f;
        #pragma unroll
        for (int i = 0; i < 8; i++) t += red[i];
        red[8] = t * (1.0f / DIM);
    }
    __syncthreads();
    float mean = red[8];
    float dx = v.x - mean, dy = v.y - mean, dz = v.z - mean, dw = v.w - mean;
    float sq = dx*dx + dy*dy + dz*dz + dw*dw;
    #pragma unroll
    for (int o = 16; o > 0; o >>= 1) sq += __shfl_xor_sync(0xffffffffu, sq, o);
    if ((tid & 31) == 0) red[tid >> 5] = sq;
    __syncthreads();
    if (tid == 0) {
        float t = 0.f;
        #pragma unroll
        for (int i = 0; i < 8; i++) t += red[i];
        red[8] = rsqrtf(t * (1.0f / DIM) + 1e-5f);
    }
    __syncthreads();
    float rstd = red[8];

    float4 wv = ((const float4*)w)[tid];
    float4 bv = ((const float4*)b)[tid];
    float4 o;
    o.x = dx * rstd * wv.x + bv.x;
    o.y = dy * rstd * wv.y + bv.y;
    o.z = dz * rstd * wv.z + bv.z;
    o.w = dw * rstd * wv.w + bv.w;
    ((float4*)(out + (size_t)row * DIM))[tid] = o;
}

// ---------------- NT GEMM: C[M,N] = A[M,K] @ B[N,K]^T (+epilogue) -------------
// 128x128x8 tiles, double-buffered smem, 8x8 per thread, 256 threads.
#define EPI_NONE      0
#define EPI_BIAS_RES  1
#define EPI_BIAS_SILU 2

template <int EPI>
__global__ __launch_bounds__(256, 2) void gemm_nt(
    const float* __restrict__ A, const float* __restrict__ Bm,
    const float* __restrict__ bias, const float* __restrict__ res,
    float* __restrict__ C, int M, int N, int K)
{
    __shared__ float As[2][8][128];
    __shared__ float Bs[2][8][128];

    int tid = threadIdx.x;
    int ty = tid >> 4;        // 0..15
    int tx = tid & 15;        // 0..15
    int bm = blockIdx.y * 128;
    int bn = blockIdx.x * 128;

    int lrow = tid >> 1;          // 0..127
    int lk   = (tid & 1) * 4;     // 0 or 4
    const float* aptr = A  + (size_t)(bm + lrow) * K + lk;
    const float* bptr = Bm + (size_t)(bn + lrow) * K + lk;

    float4 af = *(const float4*)aptr;
    float4 bf = *(const float4*)bptr;
    As[0][lk + 0][lrow] = af.x; As[0][lk + 1][lrow] = af.y;
    As[0][lk + 2][lrow] = af.z; As[0][lk + 3][lrow] = af.w;
    Bs[0][lk + 0][lrow] = bf.x; Bs[0][lk + 1][lrow] = bf.y;
    Bs[0][lk + 2][lrow] = bf.z; Bs[0][lk + 3][lrow] = bf.w;
    __syncthreads();

    float acc[8][8];
    #pragma unroll
    for (int i = 0; i < 8; i++)
        #pragma unroll
        for (int j = 0; j < 8; j++) acc[i][j] = 0.f;

    int nk = K >> 3;
    int stage = 0;
    for (int kt = 0; kt < nk; ++kt) {
        if (kt + 1 < nk) {
            af = *(const float4*)(aptr + (size_t)(kt + 1) * 8);
            bf = *(const float4*)(bptr + (size_t)(kt + 1) * 8);
        }
        #pragma unroll
        for (int k = 0; k < 8; ++k) {
            float a[8], bv[8];
            *(float4*)(a)      = *(const float4*)&As[stage][k][ty * 8];
            *(float4*)(a + 4)  = *(const float4*)&As[stage][k][ty * 8 + 4];
            *(float4*)(bv)     = *(const float4*)&Bs[stage][k][tx * 8];
            *(float4*)(bv + 4) = *(const float4*)&Bs[stage][k][tx * 8 + 4];
            #pragma unroll
            for (int i = 0; i < 8; i++)
                #pragma unroll
                for (int j = 0; j < 8; j++)
                    acc[i][j] += a[i] * bv[j];
        }
        if (kt + 1 < nk) {
            int ns = stage ^ 1;
            As[ns][lk + 0][lrow] = af.x; As[ns][lk + 1][lrow] = af.y;
            As[ns][lk + 2][lrow] = af.z; As[ns][lk + 3][lrow] = af.w;
            Bs[ns][lk + 0][lrow] = bf.x; Bs[ns][lk + 1][lrow] = bf.y;
            Bs[ns][lk + 2][lrow] = bf.z; Bs[ns][lk + 3][lrow] = bf.w;
            __syncthreads();
            stage = ns;
        }
    }

    int row0 = bm + ty * 8;
    int col0 = bn + tx * 8;
    float4 bias_lo = make_float4(0.f, 0.f, 0.f, 0.f), bias_hi = bias_lo;
    if (EPI != EPI_NONE) {
        bias_lo = *(const float4*)(bias + col0);
        bias_hi = *(const float4*)(bias + col0 + 4);
    }
    #pragma unroll
    for (int i = 0; i < 8; i++) {
        size_t base = (size_t)(row0 + i) * N + col0;
        float4 lo = make_float4(acc[i][0], acc[i][1], acc[i][2], acc[i][3]);
        float4 hi = make_float4(acc[i][4], acc[i][5], acc[i][6], acc[i][7]);
        if (EPI == EPI_BIAS_RES) {
            float4 r0 = *(const float4*)(res + base);
            float4 r1 = *(const float4*)(res + base + 4);
            lo.x += bias_lo.x + r0.x; lo.y += bias_lo.y + r0.y;
            lo.z += bias_lo.z + r0.z; lo.w += bias_lo.w + r0.w;
            hi.x += bias_hi.x + r1.x; hi.y += bias_hi.y + r1.y;
            hi.z += bias_hi.z + r1.z; hi.w += bias_hi.w + r1.w;
        } else if (EPI == EPI_BIAS_SILU) {
            lo.x += bias_lo.x; lo.y += bias_lo.y; lo.z += bias_lo.z; lo.w += bias_lo.w;
            hi.x += bias_hi.x; hi.y += bias_hi.y; hi.z += bias_hi.z; hi.w += bias_hi.w;
            lo.x *= 1.f / (1.f + __expf(-lo.x)); lo.y *= 1.f / (1.f + __expf(-lo.y));
            lo.z *= 1.f / (1.f + __expf(-lo.z)); lo.w *= 1.f / (1.f + __expf(-lo.w));
            hi.x *= 1.f / (1.f + __expf(-hi.x)); hi.y *= 1.f / (1.f + __expf(-hi.y));
            hi.z *= 1.f / (1.f + __expf(-hi.z)); hi.w *= 1.f / (1.f + __expf(-hi.w));
        }
        *(float4*)(C + base)     = lo;
        *(float4*)(C + base + 4) = hi;
    }
}

// ---------------- Flash attention: Br=Bc=64, hd=64, online softmax ------------
// grid: (32 row-blocks, 32 b*h), 256 threads.
// smem (floats): Qt[64][65](T) Kt[64][65](T) Vs[64][68] Ps[64][65] part[64][17] m,l,fac[64]
#define ATTN_SMEM_FLOATS (64*65 + 64*65 + 64*68 + 64*65 + 64*17 + 3*64)
#define ATTN_SMEM_BYTES  (ATTN_SMEM_FLOATS * 4)

__global__ __launch_bounds__(256) void attn_kernel(
    const float* __restrict__ qkv, float* __restrict__ out)
{
    extern __shared__ float sm[];
    float* Qt   = sm;                 // [d][i], stride 65
    float* Kt   = Qt + 64 * 65;      // [d][j], stride 65
    float* Vs   = Kt + 64 * 65;      // [j][d], stride 68 (float4-aligned)
    float* Ps   = Vs + 64 * 68;      // [i][j], stride 65
    float* part = Ps + 64 * 65;      // [row][16], stride 17
    float* m_s  = part + 64 * 17;
    float* l_s  = m_s + 64;
    float* fac  = l_s + 64;

    int tid = threadIdx.x;
    int ty = tid >> 4, tx = tid & 15;
    int r0 = ty * 4, c0 = tx * 4;

    int qb = blockIdx.x;                 // query block (64 rows)
    int b  = blockIdx.y >> 4;
    int h  = blockIdx.y & 15;

    const float* qbase = qkv + (size_t)(b * SEQ + qb * 64) * (3 * DIM) + h * HD;

    // load Q tile (transposed into Qt)
    for (int e = tid; e < 64 * 16; e += 256) {
        int r = e >> 4, c4 = (e & 15) * 4;
        float4 v = *(const float4*)(qbase + (size_t)r * (3 * DIM) + c4);
        Qt[(c4 + 0) * 65 + r] = v.x; Qt[(c4 + 1) * 65 + r] = v.y;
        Qt[(c4 + 2) * 65 + r] = v.z; Qt[(c4 + 3) * 65 + r] = v.w;
    }
    if (tid < 64) { m_s[tid] = -1e30f; l_s[tid] = 0.f; }

    float o_acc[4][4];
    #pragma unroll
    for (int i = 0; i < 4; i++)
        #pragma unroll
        for (int j = 0; j < 4; j++) o_acc[i][j] = 0.f;

    const float scale = 0.125f;   // 1/sqrt(64)

    for (int jb = 0; jb < SEQ / 64; ++jb) {
        __syncthreads();   // previous P@V done; Q visible on first iter
        const float* kbase = qkv + (size_t)(b * SEQ + jb * 64) * (3 * DIM) + h * HD + DIM;
        const float* vbase = kbase + DIM;
        for (int e = tid; e < 64 * 16; e += 256) {
            int r = e >> 4, c4 = (e & 15) * 4;
            float4 kv = *(const float4*)(kbase + (size_t)r * (3 * DIM) + c4);
            Kt[(c4 + 0) * 65 + r] = kv.x; Kt[(c4 + 1) * 65 + r] = kv.y;
            Kt[(c4 + 2) * 65 + r] = kv.z; Kt[(c4 + 3) * 65 + r] = kv.w;
            float4 vv = *(const float4*)(vbase + (size_t)r * (3 * DIM) + c4);
            *(float4*)&Vs[r * 68 + c4] = vv;
        }
        __syncthreads();

        // S = Q @ K^T (4x4 per thread)
        float s[4][4];
        #pragma unroll
        for (int i = 0; i < 4; i++)
            #pragma unroll
            for (int j = 0; j < 4; j++) s[i][j] = 0.f;
        #pragma unroll 4
        for (int k = 0; k < 64; ++k) {
            float a0 = Qt[k * 65 + r0 + 0], a1 = Qt[k * 65 + r0 + 1];
            float a2 = Qt[k * 65 + r0 + 2], a3 = Qt[k * 65 + r0 + 3];
            float b0 = Kt[k * 65 + c0 + 0], b1 = Kt[k * 65 + c0 + 1];
            float b2 = Kt[k * 65 + c0 + 2], b3 = Kt[k * 65 + c0 + 3];
            s[0][0] += a0*b0; s[0][1] += a0*b1; s[0][2] += a0*b2; s[0][3] += a0*b3;
            s[1][0] += a1*b0; s[1][1] += a1*b1; s[1][2] += a1*b2; s[1][3] += a1*b3;
            s[2][0] += a2*b0; s[2][1] += a2*b1; s[2][2] += a2*b2; s[2][3] += a2*b3;
            s[3][0] += a3*b0; s[3][1] += a3*b1; s[3][2] += a3*b2; s[3][3] += a3*b3;
        }
        #pragma unroll
        for (int i = 0; i < 4; i++)
            #pragma unroll
            for (int j = 0; j < 4; j++) s[i][j] *= scale;

        // row-max partials
        #pragma unroll
        for (int i = 0; i < 4; i++) {
            float pm = fmaxf(fmaxf(s[i][0], s[i][1]), fmaxf(s[i][2], s[i][3]));
            part[(r0 + i) * 17 + tx] = pm;
        }
        __syncthreads();
        if (tid < 64) {
            float mo = m_s[tid], mn = mo;
            #pragma unroll
            for (int t = 0; t < 16; t++) mn = fmaxf(mn, part[tid * 17 + t]);
            fac[tid] = __expf(mo - mn);
            m_s[tid] = mn;
        }
        __syncthreads();

        // P = exp(S - m), write to smem, partial row-sums, rescale O
        #pragma unroll
        for (int i = 0; i < 4; i++) {
            float mrow = m_s[r0 + i];
            float ps = 0.f;
            #pragma unroll
            for (int j = 0; j < 4; j++) {
                float p = __expf(s[i][j] - mrow);
                Ps[(r0 + i) * 65 + c0 + j] = p;
                ps += p;
            }
            part[(r0 + i) * 17 + tx] = ps;
            float f = fac[r0 + i];
            #pragma unroll
            for (int j = 0; j < 4; j++) o_acc[i][j] *= f;
        }
        __syncthreads();
        if (tid < 64) {
            float acc = l_s[tid] * fac[tid];
            #pragma unroll
            for (int t = 0; t < 16; t++) acc += part[tid * 17 + t];
            l_s[tid] = acc;
        }

        // O += P @ V
        #pragma unroll 4
        for (int k = 0; k < 64; ++k) {
            float p0 = Ps[(r0 + 0) * 65 + k], p1 = Ps[(r0 + 1) * 65 + k];
            float p2 = Ps[(r0 + 2) * 65 + k], p3 = Ps[(r0 + 3) * 65 + k];
            float4 v4 = *(const float4*)&Vs[k * 68 + c0];
            o_acc[0][0] += p0*v4.x; o_acc[0][1] += p0*v4.y; o_acc[0][2] += p0*v4.z; o_acc[0][3] += p0*v4.w;
            o_acc[1][0] += p1*v4.x; o_acc[1][1] += p1*v4.y; o_acc[1][2] += p1*v4.z; o_acc[1][3] += p1*v4.w;
            o_acc[2][0] += p2*v4.x; o_acc[2][1] += p2*v4.y; o_acc[2][2] += p2*v4.z; o_acc[2][3] += p2*v4.w;
            o_acc[3][0] += p3*v4.x; o_acc[3][1] += p3*v4.y; o_acc[3][2] += p3*v4.z; o_acc[3][3] += p3*v4.w;
        }
    }
    __syncthreads();   // l_s final values visible to all

    #pragma unroll
    for (int i = 0; i < 4; i++) {
        float inv = 1.0f / l_s[r0 + i];
        float4 o4 = make_float4(o_acc[i][0] * inv, o_acc[i][1] * inv,
                                o_acc[i][2] * inv, o_acc[i][3] * inv);
        size_t idx = (size_t)(b * SEQ + qb * 64 + r0 + i) * DIM + h * HD + c0;
        *(float4*)(out + idx) = o4;
    }
}

// ---------------- launch ----------------
extern "C" void kernel_launch(void* const* d_in, const int* in_sizes, int n_in,
                              void* d_out, int out_size)
{
    const float* x     = (const float*)d_in[0];
    const float* qkv_w = (const float*)d_in[1];
    const float* out_w = (const float*)d_in[2];
    const float* out_b = (const float*)d_in[3];
    const float* ff_w1 = (const float*)d_in[4];
    const float* ff_b1 = (const float*)d_in[5];
    const float* ff_w2 = (const float*)d_in[6];
    const float* ff_b2 = (const float*)d_in[7];
    const float* ln1_w = (const float*)d_in[8];
    const float* ln1_b = (const float*)d_in[9];
    const float* ln2_w = (const float*)d_in[10];
    const float* ln2_b = (const float*)d_in[11];
    float* out = (float*)d_out;

    float *xln, *qkv, *attn, *x1, *xln2, *hbuf;
    cudaGetSymbolAddress((void**)&xln,  g_xln);
    cudaGetSymbolAddress((void**)&qkv,  g_qkv);
    cudaGetSymbolAddress((void**)&attn, g_attn);
    cudaGetSymbolAddress((void**)&x1,   g_x1);
    cudaGetSymbolAddress((void**)&xln2, g_xln2);
    cudaGetSymbolAddress((void**)&hbuf, g_h);

    cudaFuncSetAttribute(attn_kernel,
        cudaFuncAttributeMaxDynamicSharedMemorySize, ATTN_SMEM_BYTES);

    // 1. LN1
    ln_kernel<<<TOK, 256>>>(x, ln1_w, ln1_b, xln);
    // 2. QKV = xln @ qkv_w^T     [4096,3072]
    gemm_nt<EPI_NONE><<<dim3(3 * DIM / 128, TOK / 128), 256>>>(
        xln, qkv_w, nullptr, nullptr, qkv, TOK, 3 * DIM, DIM);
    // 3. attention
    attn_kernel<<<dim3(SEQ / 64, 2 * NHEAD), 256, ATTN_SMEM_BYTES>>>(qkv, attn);
    // 4. x1 = x + attn @ out_w^T + out_b
    gemm_nt<EPI_BIAS_RES><<<dim3(DIM / 128, TOK / 128), 256>>>(
        attn, out_w, out_b, x, x1, TOK, DIM, DIM);
    // 5. LN2
    ln_kernel<<<TOK, 256>>>(x1, ln2_w, ln2_b, xln2);
    // 6. h = silu(xln2 @ ff_w1^T + ff_b1)   [4096,4096]
    gemm_nt<EPI_BIAS_SILU><<<dim3(MLPD / 128, TOK / 128), 256>>>(
        xln2, ff_w1, ff_b1, nullptr, hbuf, TOK, MLPD, DIM);
    // 7. out = x1 + h @ ff_w2^T + ff_b2
    gemm_nt<EPI_BIAS_RES><<<dim3(DIM / 128, TOK / 128), 256>>>(
        hbuf, ff_w2, ff_b2, x1, out, TOK, DIM, MLPD);
}

// round 2
// speedup vs baseline: 1.0833x; 1.0833x over previous
#include <cuda_runtime.h>
#include <math.h>
#include <stdint.h>

#define TOK   4096      // B*N tokens
#define DIM   1024
#define MLPD  4096
#define NHEAD 16
#define HD    64
#define SEQ   2048

// ---------------- scratch (no allocations allowed) ----------------
__device__ float g_xln [TOK * DIM];
__device__ float g_qkv [TOK * 3 * DIM];
__device__ float g_attn[TOK * DIM];
__device__ float g_x1  [TOK * DIM];
__device__ float g_xln2[TOK * DIM];
__device__ float g_h   [TOK * MLPD];

// ---------------- LayerNorm: one block per row ----------------
__global__ __launch_bounds__(256) void ln_kernel(
    const float* __restrict__ x, const float* __restrict__ w,
    const float* __restrict__ b, float* __restrict__ out)
{
    int row = blockIdx.x;
    int tid = threadIdx.x;
    const float4* xr = (const float4*)(x + (size_t)row * DIM);
    float4 v = xr[tid];

    __shared__ float red[9];
    float s = v.x + v.y + v.z + v.w;
    #pragma unroll
    for (int o = 16; o > 0; o >>= 1) s += __shfl_xor_sync(0xffffffffu, s, o);
    if ((tid & 31) == 0) red[tid >> 5] = s;
    __syncthreads();
    if (tid == 0) {
        float t = 0.f;
        #pragma unroll
        for (int i = 0; i < 8; i++) t += red[i];
        red[8] = t * (1.0f / DIM);
    }
    __syncthreads();
    float mean = red[8];
    float dx = v.x - mean, dy = v.y - mean, dz = v.z - mean, dw = v.w - mean;
    float sq = dx*dx + dy*dy + dz*dz + dw*dw;
    #pragma unroll
    for (int o = 16; o > 0; o >>= 1) sq += __shfl_xor_sync(0xffffffffu, sq, o);
    if ((tid & 31) == 0) red[tid >> 5] = sq;
    __syncthreads();
    if (tid == 0) {
        float t = 0.f;
        #pragma unroll
        for (int i = 0; i < 8; i++) t += red[i];
        red[8] = rsqrtf(t * (1.0f / DIM) + 1e-5f);
    }
    __syncthreads();
    float rstd = red[8];

    float4 wv = ((const float4*)w)[tid];
    float4 bv = ((const float4*)b)[tid];
    float4 o;
    o.x = dx * rstd * wv.x + bv.x;
    o.y = dy * rstd * wv.y + bv.y;
    o.z = dz * rstd * wv.z + bv.z;
    o.w = dw * rstd * wv.w + bv.w;
    ((float4*)(out + (size_t)row * DIM))[tid] = o;
}

// ---------------- tf32 helpers ----------------
__device__ __forceinline__ void split_tf32(float v, uint32_t& hi, uint32_t& lo) {
    uint32_t h;
    asm("cvt.rna.tf32.f32 %0, %1;" : "=r"(h) : "f"(v));
    float l = v - __uint_as_float(h);
    uint32_t lw;
    asm("cvt.rna.tf32.f32 %0, %1;" : "=r"(lw) : "f"(l));
    hi = h; lo = lw;
}

__device__ __forceinline__ void mma_tf32(float* d, const uint32_t* a, const uint32_t* b) {
    asm volatile(
        "mma.sync.aligned.m16n8k8.row.col.f32.tf32.tf32.f32 "
        "{%0,%1,%2,%3}, {%4,%5,%6,%7}, {%8,%9}, {%0,%1,%2,%3};"
        : "+f"(d[0]), "+f"(d[1]), "+f"(d[2]), "+f"(d[3])
        : "r"(a[0]), "r"(a[1]), "r"(a[2]), "r"(a[3]), "r"(b[0]), "r"(b[1]));
}

#define CP_ASYNC16(dst_u32, src_ptr) \
    asm volatile("cp.async.ca.shared.global [%0], [%1], 16;" \
                 :: "r"(dst_u32), "l"(src_ptr) : "memory")
#define CP_COMMIT() asm volatile("cp.async.commit_group;" ::: "memory")
#define CP_WAIT0()  asm volatile("cp.async.wait_group 0;" ::: "memory")

// ---------------- NT GEMM (3xTF32): C[M,N] = A[M,K] @ B[N,K]^T + epilogue ----
// 128x128 CTA tile, KT=16, cp.async double buffer, 8 warps each 64x32.
#define EPI_NONE      0
#define EPI_BIAS_RES  1
#define EPI_BIAS_SILU 2

#define KT   16
#define GSTR 20   // smem row stride in floats (bank-conflict-free fragment loads)

template <int EPI>
__global__ __launch_bounds__(256, 2) void gemm_tf32(
    const float* __restrict__ A, const float* __restrict__ Bm,
    const float* __restrict__ bias, const float* __restrict__ res,
    float* __restrict__ C, int M, int N, int K)
{
    __shared__ float As[2][128][GSTR];
    __shared__ float Bs[2][128][GSTR];

    int tid  = threadIdx.x;
    int bm   = blockIdx.y * 128;
    int bn   = blockIdx.x * 128;
    int warp = tid >> 5, lane = tid & 31;
    int wm   = (warp & 1) * 64;       // warp row offset (2 warps in m)
    int wn   = (warp >> 1) * 32;      // warp col offset (4 warps in n)
    int gid  = lane >> 2, tig = lane & 3;

    // load assignment: each thread owns row lr (of A and of B), k-halves lk..lk+7
    int lr = tid & 127;
    int lk = (tid >> 7) * 8;
    const float* ag = A  + (size_t)(bm + lr) * K + lk;
    const float* bg = Bm + (size_t)(bn + lr) * K + lk;

    uint32_t a_smem = (uint32_t)__cvta_generic_to_shared(&As[0][lr][lk]);
    uint32_t b_smem = (uint32_t)__cvta_generic_to_shared(&Bs[0][lr][lk]);
    const uint32_t stage_bytes = 128 * GSTR * 4;

    float acc[4][4][4];
    #pragma unroll
    for (int i = 0; i < 4; i++)
        #pragma unroll
        for (int j = 0; j < 4; j++)
            #pragma unroll
            for (int r = 0; r < 4; r++) acc[i][j][r] = 0.f;

    int ntiles = K / KT;

    // prologue: tile 0 into stage 0
    CP_ASYNC16(a_smem,      ag);
    CP_ASYNC16(a_smem + 16, ag + 4);
    CP_ASYNC16(b_smem,      bg);
    CP_ASYNC16(b_smem + 16, bg + 4);
    CP_COMMIT();

    for (int t = 0; t < ntiles; ++t) {
        CP_WAIT0();
        __syncthreads();
        if (t + 1 < ntiles) {
            uint32_t st = ((t + 1) & 1) * stage_bytes;
            const float* an = ag + (size_t)(t + 1) * KT;
            const float* bn2 = bg + (size_t)(t + 1) * KT;
            CP_ASYNC16(a_smem + st,      an);
            CP_ASYNC16(a_smem + st + 16, an + 4);
            CP_ASYNC16(b_smem + st,      bn2);
            CP_ASYNC16(b_smem + st + 16, bn2 + 4);
            CP_COMMIT();
        }
        int s = t & 1;
        #pragma unroll
        for (int ks = 0; ks < 2; ++ks) {
            int kk = ks * 8;
            // B fragments (hi/lo) for 4 n-tiles
            uint32_t bh[4][2], bl[4][2];
            #pragma unroll
            for (int nt = 0; nt < 4; ++nt) {
                int n = wn + nt * 8 + gid;
                float b0 = Bs[s][n][kk + tig];
                float b1 = Bs[s][n][kk + tig + 4];
                split_tf32(b0, bh[nt][0], bl[nt][0]);
                split_tf32(b1, bh[nt][1], bl[nt][1]);
            }
            #pragma unroll
            for (int mt = 0; mt < 4; ++mt) {
                int m0 = wm + mt * 16;
                float a0 = As[s][m0 + gid][kk + tig];
                float a1 = As[s][m0 + 8 + gid][kk + tig];
                float a2 = As[s][m0 + gid][kk + tig + 4];
                float a3 = As[s][m0 + 8 + gid][kk + tig + 4];
                uint32_t ah[4], al[4];
                split_tf32(a0, ah[0], al[0]);
                split_tf32(a1, ah[1], al[1]);
                split_tf32(a2, ah[2], al[2]);
                split_tf32(a3, ah[3], al[3]);
                #pragma unroll
                for (int nt = 0; nt < 4; ++nt) {
                    mma_tf32(acc[mt][nt], ah, bh[nt]);   // hi*hi
                    mma_tf32(acc[mt][nt], ah, bl[nt]);   // hi*lo
                    mma_tf32(acc[mt][nt], al, bh[nt]);   // lo*hi
                }
            }
        }
        __syncthreads();
    }

    // epilogue
    #pragma unroll
    for (int mt = 0; mt < 4; ++mt) {
        #pragma unroll
        for (int nt = 0; nt < 4; ++nt) {
            int row = bm + wm + mt * 16 + gid;
            int col = bn + wn + nt * 8 + tig * 2;
            float2 v0 = make_float2(acc[mt][nt][0], acc[mt][nt][1]);
            float2 v1 = make_float2(acc[mt][nt][2], acc[mt][nt][3]);
            if (EPI != EPI_NONE) {
                float bx = bias[col], by = bias[col + 1];
                v0.x += bx; v0.y += by; v1.x += bx; v1.y += by;
            }
            if (EPI == EPI_BIAS_RES) {
                float2 r0 = *(const float2*)(res + (size_t)row * N + col);
                float2 r1 = *(const float2*)(res + (size_t)(row + 8) * N + col);
                v0.x += r0.x; v0.y += r0.y; v1.x += r1.x; v1.y += r1.y;
            } else if (EPI == EPI_BIAS_SILU) {
                v0.x *= 1.f / (1.f + __expf(-v0.x));
                v0.y *= 1.f / (1.f + __expf(-v0.y));
                v1.x *= 1.f / (1.f + __expf(-v1.x));
                v1.y *= 1.f / (1.f + __expf(-v1.y));
            }
            *(float2*)(C + (size_t)row * N + col)       = v0;
            *(float2*)(C + (size_t)(row + 8) * N + col) = v1;
        }
    }
}

// ---------------- Flash attention: Br=Bc=64, hd=64, online softmax ------------
#define ATTN_SMEM_FLOATS (64*65 + 64*65 + 64*68 + 64*65 + 64*17 + 3*64)
#define ATTN_SMEM_BYTES  (ATTN_SMEM_FLOATS * 4)

__global__ __launch_bounds__(256) void attn_kernel(
    const float* __restrict__ qkv, float* __restrict__ out)
{
    extern __shared__ float sm[];
    float* Qt   = sm;                 // [d][i], stride 65
    float* Kt   = Qt + 64 * 65;      // [d][j], stride 65
    float* Vs   = Kt + 64 * 65;      // [j][d], stride 68
    float* Ps   = Vs + 64 * 68;      // [i][j], stride 65
    float* part = Ps + 64 * 65;      // [row][16], stride 17
    float* m_s  = part + 64 * 17;
    float* l_s  = m_s + 64;
    float* fac  = l_s + 64;

    int tid = threadIdx.x;
    int ty = tid >> 4, tx = tid & 15;
    int r0 = ty * 4, c0 = tx * 4;

    int qb = blockIdx.x;
    int b  = blockIdx.y >> 4;
    int h  = blockIdx.y & 15;

    const float* qbase = qkv + (size_t)(b * SEQ + qb * 64) * (3 * DIM) + h * HD;

    for (int e = tid; e < 64 * 16; e += 256) {
        int r = e >> 4, c4 = (e & 15) * 4;
        float4 v = *(const float4*)(qbase + (size_t)r * (3 * DIM) + c4);
        Qt[(c4 + 0) * 65 + r] = v.x; Qt[(c4 + 1) * 65 + r] = v.y;
        Qt[(c4 + 2) * 65 + r] = v.z; Qt[(c4 + 3) * 65 + r] = v.w;
    }
    if (tid < 64) { m_s[tid] = -1e30f; l_s[tid] = 0.f; }

    float o_acc[4][4];
    #pragma unroll
    for (int i = 0; i < 4; i++)
        #pragma unroll
        for (int j = 0; j < 4; j++) o_acc[i][j] = 0.f;

    const float scale = 0.125f;

    for (int jb = 0; jb < SEQ / 64; ++jb) {
        __syncthreads();
        const float* kbase = qkv + (size_t)(b * SEQ + jb * 64) * (3 * DIM) + h * HD + DIM;
        const float* vbase = kbase + DIM;
        for (int e = tid; e < 64 * 16; e += 256) {
            int r = e >> 4, c4 = (e & 15) * 4;
            float4 kv = *(const float4*)(kbase + (size_t)r * (3 * DIM) + c4);
            Kt[(c4 + 0) * 65 + r] = kv.x; Kt[(c4 + 1) * 65 + r] = kv.y;
            Kt[(c4 + 2) * 65 + r] = kv.z; Kt[(c4 + 3) * 65 + r] = kv.w;
            float4 vv = *(const float4*)(vbase + (size_t)r * (3 * DIM) + c4);
            *(float4*)&Vs[r * 68 + c4] = vv;
        }
        __syncthreads();

        float s[4][4];
        #pragma unroll
        for (int i = 0; i < 4; i++)
            #pragma unroll
            for (int j = 0; j < 4; j++) s[i][j] = 0.f;
        #pragma unroll 4
        for (int k = 0; k < 64; ++k) {
            float a0 = Qt[k * 65 + r0 + 0], a1 = Qt[k * 65 + r0 + 1];
            float a2 = Qt[k * 65 + r0 + 2], a3 = Qt[k * 65 + r0 + 3];
            float b0 = Kt[k * 65 + c0 + 0], b1 = Kt[k * 65 + c0 + 1];
            float b2 = Kt[k * 65 + c0 + 2], b3 = Kt[k * 65 + c0 + 3];
            s[0][0] += a0*b0; s[0][1] += a0*b1; s[0][2] += a0*b2; s[0][3] += a0*b3;
            s[1][0] += a1*b0; s[1][1] += a1*b1; s[1][2] += a1*b2; s[1][3] += a1*b3;
            s[2][0] += a2*b0; s[2][1] += a2*b1; s[2][2] += a2*b2; s[2][3] += a2*b3;
            s[3][0] += a3*b0; s[3][1] += a3*b1; s[3][2] += a3*b2; s[3][3] += a3*b3;
        }
        #pragma unroll
        for (int i = 0; i < 4; i++)
            #pragma unroll
            for (int j = 0; j < 4; j++) s[i][j] *= scale;

        #pragma unroll
        for (int i = 0; i < 4; i++) {
            float pm = fmaxf(fmaxf(s[i][0], s[i][1]), fmaxf(s[i][2], s[i][3]));
            part[(r0 + i) * 17 + tx] = pm;
        }
        __syncthreads();
        if (tid < 64) {
            float mo = m_s[tid], mn = mo;
            #pragma unroll
            for (int t = 0; t < 16; t++) mn = fmaxf(mn, part[tid * 17 + t]);
            fac[tid] = __expf(mo - mn);
            m_s[tid] = mn;
        }
        __syncthreads();

        #pragma unroll
        for (int i = 0; i < 4; i++) {
            float mrow = m_s[r0 + i];
            float ps = 0.f;
            #pragma unroll
            for (int j = 0; j < 4; j++) {
                float p = __expf(s[i][j] - mrow);
                Ps[(r0 + i) * 65 + c0 + j] = p;
                ps += p;
            }
            part[(r0 + i) * 17 + tx] = ps;
            float f = fac[r0 + i];
            #pragma unroll
            for (int j = 0; j < 4; j++) o_acc[i][j] *= f;
        }
        __syncthreads();
        if (tid < 64) {
            float acc2 = l_s[tid] * fac[tid];
            #pragma unroll
            for (int t = 0; t < 16; t++) acc2 += part[tid * 17 + t];
            l_s[tid] = acc2;
        }

        #pragma unroll 4
        for (int k = 0; k < 64; ++k) {
            float p0 = Ps[(r0 + 0) * 65 + k], p1 = Ps[(r0 + 1) * 65 + k];
            float p2 = Ps[(r0 + 2) * 65 + k], p3 = Ps[(r0 + 3) * 65 + k];
            float4 v4 = *(const float4*)&Vs[k * 68 + c0];
            o_acc[0][0] += p0*v4.x; o_acc[0][1] += p0*v4.y; o_acc[0][2] += p0*v4.z; o_acc[0][3] += p0*v4.w;
            o_acc[1][0] += p1*v4.x; o_acc[1][1] += p1*v4.y; o_acc[1][2] += p1*v4.z; o_acc[1][3] += p1*v4.w;
            o_acc[2][0] += p2*v4.x; o_acc[2][1] += p2*v4.y; o_acc[2][2] += p2*v4.z; o_acc[2][3] += p2*v4.w;
            o_acc[3][0] += p3*v4.x; o_acc[3][1] += p3*v4.y; o_acc[3][2] += p3*v4.z; o_acc[3][3] += p3*v4.w;
        }
    }
    __syncthreads();

    #pragma unroll
    for (int i = 0; i < 4; i++) {
        float inv = 1.0f / l_s[r0 + i];
        float4 o4 = make_float4(o_acc[i][0] * inv, o_acc[i][1] * inv,
                                o_acc[i][2] * inv, o_acc[i][3] * inv);
        size_t idx = (size_t)(b * SEQ + qb * 64 + r0 + i) * DIM + h * HD + c0;
        *(float4*)(out + idx) = o4;
    }
}

// ---------------- launch ----------------
extern "C" void kernel_launch(void* const* d_in, const int* in_sizes, int n_in,
                              void* d_out, int out_size)
{
    const float* x     = (const float*)d_in[0];
    const float* qkv_w = (const float*)d_in[1];
    const float* out_w = (const float*)d_in[2];
    const float* out_b = (const float*)d_in[3];
    const float* ff_w1 = (const float*)d_in[4];
    const float* ff_b1 = (const float*)d_in[5];
    const float* ff_w2 = (const float*)d_in[6];
    const float* ff_b2 = (const float*)d_in[7];
    const float* ln1_w = (const float*)d_in[8];
    const float* ln1_b = (const float*)d_in[9];
    const float* ln2_w = (const float*)d_in[10];
    const float* ln2_b = (const float*)d_in[11];
    float* out = (float*)d_out;

    float *xln, *qkv, *attn, *x1, *xln2, *hbuf;
    cudaGetSymbolAddress((void**)&xln,  g_xln);
    cudaGetSymbolAddress((void**)&qkv,  g_qkv);
    cudaGetSymbolAddress((void**)&attn, g_attn);
    cudaGetSymbolAddress((void**)&x1,   g_x1);
    cudaGetSymbolAddress((void**)&xln2, g_xln2);
    cudaGetSymbolAddress((void**)&hbuf, g_h);

    cudaFuncSetAttribute(attn_kernel,
        cudaFuncAttributeMaxDynamicSharedMemorySize, ATTN_SMEM_BYTES);

    // 1. LN1
    ln_kernel<<<TOK, 256>>>(x, ln1_w, ln1_b, xln);
    // 2. QKV = xln @ qkv_w^T     [4096,3072]
    gemm_tf32<EPI_NONE><<<dim3(3 * DIM / 128, TOK / 128), 256>>>(
        xln, qkv_w, nullptr, nullptr, qkv, TOK, 3 * DIM, DIM);
    // 3. attention
    attn_kernel<<<dim3(SEQ / 64, 2 * NHEAD), 256, ATTN_SMEM_BYTES>>>(qkv, attn);
    // 4. x1 = x + attn @ out_w^T + out_b
    gemm_tf32<EPI_BIAS_RES><<<dim3(DIM / 128, TOK / 128), 256>>>(
        attn, out_w, out_b, x, x1, TOK, DIM, DIM);
    // 5. LN2
    ln_kernel<<<TOK, 256>>>(x1, ln2_w, ln2_b, xln2);
    // 6. h = silu(xln2 @ ff_w1^T + ff_b1)   [4096,4096]
    gemm_tf32<EPI_BIAS_SILU><<<dim3(MLPD / 128, TOK / 128), 256>>>(
        xln2, ff_w1, ff_b1, nullptr, hbuf, TOK, MLPD, DIM);
    // 7. out = x1 + h @ ff_w2^T + ff_b2
    gemm_tf32<EPI_BIAS_RES><<<dim3(DIM / 128, TOK / 128), 256>>>(
        hbuf, ff_w2, ff_b2, x1, out, TOK, DIM, MLPD);
}